// round 15
// baseline (speedup 1.0000x reference)
#include <cuda_runtime.h>
#include <cuda_fp16.h>
#include <cstdint>

#define T_TOKENS 4096
#define H_DIM    2048
#define I_DIM    1408
#define E_NUM    16
#define SI_DIM   2816
#define SLOTS    8192   // T * TOP_K

// ---------------- scratch (device globals; no runtime allocation) ----------
__device__ int   g_cnt[E_NUM];
__device__ int   g_off[E_NUM];
__device__ int   g_cur[E_NUM];
__device__ int   g_eid[T_TOKENS * 2];
__device__ float g_wgt[T_TOKENS * 2];
__device__ int   g_rowtok[SLOTS];
__device__ float g_slotw[SLOTS];

// fp16 operands (all natural layout; no transposes)
__device__ __half g_xf[T_TOKENS * H_DIM];
__device__ __half g_sgf[H_DIM * SI_DIM];
__device__ __half g_suf[H_DIM * SI_DIM];
__device__ __half g_sdf[SI_DIM * H_DIM];
__device__ __half g_wgf[E_NUM * H_DIM * I_DIM];
__device__ __half g_wuf[E_NUM * H_DIM * I_DIM];
__device__ __half g_wdf[E_NUM * I_DIM * H_DIM];
// intermediate activations
__device__ __half g_hsf[T_TOKENS * SI_DIM];
__device__ __half g_hrf[SLOTS * I_DIM];

// ---------------- threefry2x32 core (verified vs Random123 KAT) -------------
__device__ __forceinline__ uint32_t rotl32(uint32_t v, int r) {
    return (v << r) | (v >> (32 - r));
}

__device__ __forceinline__ void threefry2x32(uint32_t x0, uint32_t x1,
                                             uint32_t& o0, uint32_t& o1) {
    const uint32_t ks0 = 0u, ks1 = 42u, ks2 = 0u ^ 42u ^ 0x1BD11BDAu;
    x0 += ks0; x1 += ks1;
    x0 += x1; x1 = rotl32(x1, 13); x1 ^= x0;
    x0 += x1; x1 = rotl32(x1, 15); x1 ^= x0;
    x0 += x1; x1 = rotl32(x1, 26); x1 ^= x0;
    x0 += x1; x1 = rotl32(x1, 6);  x1 ^= x0;
    x0 += ks1; x1 += ks2 + 1u;
    x0 += x1; x1 = rotl32(x1, 17); x1 ^= x0;
    x0 += x1; x1 = rotl32(x1, 29); x1 ^= x0;
    x0 += x1; x1 = rotl32(x1, 16); x1 ^= x0;
    x0 += x1; x1 = rotl32(x1, 24); x1 ^= x0;
    x0 += ks2; x1 += ks0 + 2u;
    x0 += x1; x1 = rotl32(x1, 13); x1 ^= x0;
    x0 += x1; x1 = rotl32(x1, 15); x1 ^= x0;
    x0 += x1; x1 = rotl32(x1, 26); x1 ^= x0;
    x0 += x1; x1 = rotl32(x1, 6);  x1 ^= x0;
    x0 += ks0; x1 += ks1 + 3u;
    x0 += x1; x1 = rotl32(x1, 17); x1 ^= x0;
    x0 += x1; x1 = rotl32(x1, 29); x1 ^= x0;
    x0 += x1; x1 = rotl32(x1, 16); x1 ^= x0;
    x0 += x1; x1 = rotl32(x1, 24); x1 ^= x0;
    x0 += ks1; x1 += ks2 + 4u;
    x0 += x1; x1 = rotl32(x1, 13); x1 ^= x0;
    x0 += x1; x1 = rotl32(x1, 15); x1 ^= x0;
    x0 += x1; x1 = rotl32(x1, 26); x1 ^= x0;
    x0 += x1; x1 = rotl32(x1, 6);  x1 ^= x0;
    x0 += ks2; x1 += ks0 + 5u;
    o0 = x0; o1 = x1;
}

__device__ __forceinline__ float erfinv_xla(float x) {
    float w = -log1pf(-x * x);
    float p;
    if (w < 5.0f) {
        w -= 2.5f;
        p = 2.81022636e-08f;
        p = fmaf(p, w, 3.43273939e-07f);
        p = fmaf(p, w, -3.5233877e-06f);
        p = fmaf(p, w, -4.39150654e-06f);
        p = fmaf(p, w, 0.00021858087f);
        p = fmaf(p, w, -0.00125372503f);
        p = fmaf(p, w, -0.00417768164f);
        p = fmaf(p, w, 0.246640727f);
        p = fmaf(p, w, 1.50140941f);
    } else {
        w = sqrtf(w) - 3.0f;
        p = -0.000200214257f;
        p = fmaf(p, w, 0.000100950558f);
        p = fmaf(p, w, 0.00134934322f);
        p = fmaf(p, w, -0.00367342844f);
        p = fmaf(p, w, 0.00573950773f);
        p = fmaf(p, w, -0.0076224613f);
        p = fmaf(p, w, 0.00943887047f);
        p = fmaf(p, w, 1.00167406f);
        p = fmaf(p, w, 2.83297682f);
    }
    return p * x;
}

// ---------------- routing kernels ------------------------------------------
__global__ void zero_kernel() {
    if (threadIdx.x < E_NUM) g_cnt[threadIdx.x] = 0;
}

__global__ void route_kernel() {
    int t = blockIdx.x * blockDim.x + threadIdx.x;
    if (t >= T_TOKENS) return;
    float s[E_NUM];
#pragma unroll
    for (int e = 0; e < E_NUM; ++e) {
        uint32_t i = (uint32_t)t * E_NUM + (uint32_t)e;
        uint32_t o0, o1;
        threefry2x32(0u, i, o0, o1);
        uint32_t bits = o0 ^ o1;
        float u01 = __uint_as_float((bits >> 9) | 0x3f800000u) - 1.0f;
        float u = fmaf(u01, 2.0f, -0.99999994f);
        u = fmaxf(-0.99999994f, u);
        float nz = 1.4142135381698608f * erfinv_xla(u);
        s[e] = 1.0f / (1.0f + expf(-nz));
    }
    int b0 = 0;
#pragma unroll
    for (int e = 1; e < E_NUM; ++e) if (s[e] > s[b0]) b0 = e;
    int b1 = (b0 == 0) ? 1 : 0;
#pragma unroll
    for (int e = 0; e < E_NUM; ++e) if (e != b0 && s[e] > s[b1]) b1 = e;
    float sum = s[b0] + s[b1] + 1e-8f;
    g_eid[2 * t + 0] = b0;
    g_eid[2 * t + 1] = b1;
    g_wgt[2 * t + 0] = s[b0] / sum;
    g_wgt[2 * t + 1] = s[b1] / sum;
    atomicAdd(&g_cnt[b0], 1);
    atomicAdd(&g_cnt[b1], 1);
}

__global__ void scan_kernel() {
    int a = 0;
    for (int e = 0; e < E_NUM; ++e) { g_off[e] = a; g_cur[e] = a; a += g_cnt[e]; }
}

__global__ void scatter_kernel() {
    int t = blockIdx.x * blockDim.x + threadIdx.x;
    if (t >= T_TOKENS) return;
#pragma unroll
    for (int k = 0; k < 2; ++k) {
        int e = g_eid[2 * t + k];
        int sidx = atomicAdd(&g_cur[e], 1);
        g_rowtok[sidx] = t;
        g_slotw[sidx]  = g_wgt[2 * t + k];
    }
}

// ---------------- grid-stride streaming conversion (MLP=4) ------------------
__global__ void conv_f16(const float* __restrict__ src,
                         __half* __restrict__ dst, size_t n16) {
    size_t g = (size_t)blockIdx.x * blockDim.x + threadIdx.x;
    size_t gs = (size_t)gridDim.x * blockDim.x;
    for (size_t c = g; c < n16; c += gs) {
        const float4* s4 = (const float4*)(src + c * 16);
        float4 v[4];
#pragma unroll
        for (int j = 0; j < 4; ++j) v[j] = s4[j];
        uint2* d4 = (uint2*)(dst + c * 16);
#pragma unroll
        for (int j = 0; j < 4; ++j) {
            __half f[4];
            f[0] = __float2half_rn(v[j].x);
            f[1] = __float2half_rn(v[j].y);
            f[2] = __float2half_rn(v[j].z);
            f[3] = __float2half_rn(v[j].w);
            d4[j] = *(uint2*)f;
        }
    }
}

// ---------------- warp-MMA helpers ------------------------------------------
__device__ __forceinline__ uint32_t smem_u32(const void* p) {
    uint32_t a;
    asm("{ .reg .u64 t; cvta.to.shared.u64 t, %1; cvt.u32.u64 %0, t; }"
        : "=r"(a) : "l"(p));
    return a;
}

__device__ __forceinline__ void cp16(uint32_t s, const void* g) {
    asm volatile("cp.async.cg.shared.global [%0], [%1], 16;"
                 :: "r"(s), "l"(g) : "memory");
}
#define CP_COMMIT() asm volatile("cp.async.commit_group;" ::: "memory")
template <int N>
__device__ __forceinline__ void cp_wait() {
    asm volatile("cp.async.wait_group %0;" :: "n"(N) : "memory");
}

__device__ __forceinline__ void ldsm4(uint32_t* r, uint32_t a) {
    asm volatile("ldmatrix.sync.aligned.m8n8.x4.shared.b16 {%0,%1,%2,%3}, [%4];"
                 : "=r"(r[0]), "=r"(r[1]), "=r"(r[2]), "=r"(r[3]) : "r"(a));
}
__device__ __forceinline__ void ldsm4t(uint32_t* r, uint32_t a) {
    asm volatile("ldmatrix.sync.aligned.m8n8.x4.trans.shared.b16 {%0,%1,%2,%3}, [%4];"
                 : "=r"(r[0]), "=r"(r[1]), "=r"(r[2]), "=r"(r[3]) : "r"(a));
}

__device__ __forceinline__ void mma_f16(float* c, const uint32_t* a,
                                        uint32_t b0, uint32_t b1) {
    asm volatile(
        "mma.sync.aligned.m16n8k16.row.col.f32.f16.f16.f32 "
        "{%0,%1,%2,%3}, {%4,%5,%6,%7}, {%8,%9}, {%0,%1,%2,%3};"
        : "+f"(c[0]), "+f"(c[1]), "+f"(c[2]), "+f"(c[3])
        : "r"(a[0]), "r"(a[1]), "r"(a[2]), "r"(a[3]), "r"(b0), "r"(b1));
}

__device__ __forceinline__ float swiglu_f(float g, float u) {
    return (g / (1.0f + expf(-g))) * u;
}

// A-tile swizzle (128B rows)
__device__ __forceinline__ uint32_t swzA(uint32_t off) {
    return off ^ ((off >> 3) & 0x70u);
}

// =============================================================================
// FUSED gate+up GEMM (fp16 single-pass). A k-major [M][K]; B natural [K][N]
// via ldmatrix.trans. Epilogue -> fp16 swiglu acts.
// CTA 128x128, KC=64, 3 stages (48KB/stage), 8 warps (2x4), warp tile 64x32.
// =============================================================================
template <bool ROUTED, bool GATHER>
__global__ void __launch_bounds__(256, 1)
mma_fused(const __half* __restrict__ Af,
          const __half* __restrict__ B1f, const __half* __restrict__ B2f,
          __half* __restrict__ Ohf, int K, int N, int fixedM)
{
    constexpr int KC   = 64;
    constexpr int TILE = KC * 256;     // 16 KB
    constexpr int STG  = 3 * TILE;     // 48 KB
    constexpr int OF_B1 = TILE;
    constexpr int OF_B2 = 2 * TILE;

    extern __shared__ char smem[];
    const int tid  = threadIdx.x;
    const int wid  = tid >> 5;
    const int lane = tid & 31;

    const int e = blockIdx.z;
    int M, seg;
    if (ROUTED) { M = g_cnt[e]; seg = g_off[e]; }
    else        { M = fixedM;   seg = 0; }
    const int mbase = blockIdx.y * 128;
    if (mbase >= M) return;
    const int nbase = blockIdx.x * 128;

    const uint32_t sb = smem_u32(smem);

    const int lrow = tid >> 1;
    const int hbA  = (tid & 1) * 64;
    uint32_t soA[4];
#pragma unroll
    for (int j = 0; j < 4; ++j)
        soA[j] = swzA((uint32_t)lrow * 128u + (uint32_t)hbA + j * 16u);

    int arow;
    {
        bool v = (mbase + lrow) < M;
        if (ROUTED) {
            int slot = seg + mbase + lrow;
            if (GATHER) arow = v ? g_rowtok[slot] : 0;
            else        arow = v ? slot : seg;
        } else arow = mbase + lrow;
    }
    const char* gA = (const char*)(Af + (size_t)arow * K) + hbA;

    const int bk  = tid >> 2;
    const int bnb = (tid & 3) * 64;
    uint32_t soB[4];
#pragma unroll
    for (int j = 0; j < 4; ++j)
        soB[j] = (uint32_t)bk * 256u + (((uint32_t)bnb + j * 16u) ^ (((uint32_t)bk & 7u) << 4));

    const size_t bexp = ROUTED ? (size_t)e * (size_t)K * (size_t)N : 0;
    const size_t brow = bexp + (size_t)bk * N + nbase;
    const char* gB1 = (const char*)(B1f + brow) + bnb;
    const char* gB2 = (const char*)(B2f + brow) + bnb;
    const size_t bstep = (size_t)KC * N * 2;

    const int nk = K / KC;

#define ISSUE_F(slot, kt)                                                       \
    do {                                                                        \
        uint32_t b_ = sb + (uint32_t)(slot) * STG;                              \
        size_t ak_ = (size_t)(kt) * 128;                                        \
        size_t bk_ = (size_t)(kt) * bstep;                                      \
        _Pragma("unroll")                                                       \
        for (int j_ = 0; j_ < 4; ++j_) {                                        \
            cp16(b_ + soA[j_],         gA  + ak_ + j_ * 16);                    \
            cp16(b_ + OF_B1 + soB[j_], gB1 + bk_ + j_ * 16);                    \
            cp16(b_ + OF_B2 + soB[j_], gB2 + bk_ + j_ * 16);                    \
        }                                                                       \
        CP_COMMIT();                                                            \
    } while (0)

    const int wm = (wid >> 2) * 64;
    const int wn = (wid & 3) * 32;

    uint32_t aOff[4];
#pragma unroll
    for (int mf = 0; mf < 4; ++mf)
        aOff[mf] = (uint32_t)(wm + mf * 16 + (lane & 15)) * 128u
                 + (uint32_t)((lane >> 4) * 16);
    uint32_t bB[2];
    {
        uint32_t r = lane & 7u, m = lane >> 3;
#pragma unroll
        for (int nf2 = 0; nf2 < 2; ++nf2) {
            uint32_t nb = (uint32_t)(wn + nf2 * 16 + (int)((m >> 1) * 8)) * 2u;
            bB[nf2] = ((m & 1u) * 8u + r) * 256u + (nb ^ (r << 4));
        }
    }

    float accG[4][4][4], accU[4][4][4];
#pragma unroll
    for (int i = 0; i < 4; ++i)
#pragma unroll
        for (int j = 0; j < 4; ++j)
#pragma unroll
            for (int q = 0; q < 4; ++q) { accG[i][j][q] = 0.f; accU[i][j][q] = 0.f; }

    ISSUE_F(0, 0);
    ISSUE_F(1, 1);

    for (int kt = 0; kt < nk; ++kt) {
        const int s = kt % 3;
        if (kt + 1 < nk) cp_wait<1>(); else cp_wait<0>();
        __syncthreads();
        if (kt + 2 < nk) ISSUE_F((kt + 2) % 3, kt + 2);

        const uint32_t stb = sb + (uint32_t)s * STG;
#pragma unroll
        for (int ks = 0; ks < 4; ++ks) {
            uint32_t a[4][4], b1[2][4], b2[2][4];
#pragma unroll
            for (int mf = 0; mf < 4; ++mf)
                ldsm4(a[mf], stb + swzA(aOff[mf] + ks * 32u));
#pragma unroll
            for (int nf2 = 0; nf2 < 2; ++nf2) {
                uint32_t off = bB[nf2] + ks * 4096u;
                ldsm4t(b1[nf2], stb + OF_B1 + off);
                ldsm4t(b2[nf2], stb + OF_B2 + off);
            }
#pragma unroll
            for (int mf = 0; mf < 4; ++mf)
#pragma unroll
                for (int nf = 0; nf < 4; ++nf)
                    mma_f16(accG[mf][nf], a[mf],
                            b1[nf >> 1][(nf & 1) * 2], b1[nf >> 1][(nf & 1) * 2 + 1]);
#pragma unroll
            for (int mf = 0; mf < 4; ++mf)
#pragma unroll
                for (int nf = 0; nf < 4; ++nf)
                    mma_f16(accU[mf][nf], a[mf],
                            b2[nf >> 1][(nf & 1) * 2], b2[nf >> 1][(nf & 1) * 2 + 1]);
        }
    }
#undef ISSUE_F

    const size_t rowoff = ROUTED ? (size_t)seg : 0;
#pragma unroll
    for (int mf = 0; mf < 4; ++mf) {
#pragma unroll
        for (int nf = 0; nf < 4; ++nf) {
            int r0 = mbase + wm + mf * 16 + (lane >> 2);
            int n0 = nbase + wn + nf * 8 + (lane & 3) * 2;
            float* cg = accG[mf][nf];
            float* cu = accU[mf][nf];
#pragma unroll
            for (int h = 0; h < 2; ++h) {
                int r = r0 + h * 8;
                if (r < M) {
                    size_t idx = (rowoff + r) * (size_t)N + n0;
                    float a0 = swiglu_f(cg[h * 2 + 0], cu[h * 2 + 0]);
                    float a1 = swiglu_f(cg[h * 2 + 1], cu[h * 2 + 1]);
                    __half2 hp = __floats2half2_rn(a0, a1);
                    *(uint32_t*)&Ohf[idx] = *reinterpret_cast<uint32_t*>(&hp);
                }
            }
        }
    }
}

// =============================================================================
// DOWN GEMM (fp16 single-pass). A k-major; B natural [K][N].
// !ROUTED: plain fp32 store (full overwrite of out).
// ROUTED:  fused combine — atomicAdd(out[token], slot_weight * acc).
// CTA 128x128, KC=64, 3 stages (32KB/stage).
// =============================================================================
template <bool ROUTED>
__global__ void __launch_bounds__(256, 1)
mma_down(const __half* __restrict__ Af, const __half* __restrict__ Bf,
         float* __restrict__ Cf, int K, int N, int fixedM)
{
    constexpr int KC   = 64;
    constexpr int TILE = KC * 256;
    constexpr int STG  = 2 * TILE;     // 32 KB
    constexpr int OF_B = TILE;

    extern __shared__ char smem[];
    const int tid  = threadIdx.x;
    const int wid  = tid >> 5;
    const int lane = tid & 31;

    const int e = blockIdx.z;
    int M, seg;
    if (ROUTED) { M = g_cnt[e]; seg = g_off[e]; }
    else        { M = fixedM;   seg = 0; }
    const int mbase = blockIdx.y * 128;
    if (mbase >= M) return;
    const int nbase = blockIdx.x * 128;

    const uint32_t sb = smem_u32(smem);

    const int lrow = tid >> 1;
    const int hbA  = (tid & 1) * 64;
    uint32_t soA[4];
#pragma unroll
    for (int j = 0; j < 4; ++j)
        soA[j] = swzA((uint32_t)lrow * 128u + (uint32_t)hbA + j * 16u);

    int arow;
    {
        bool v = (mbase + lrow) < M;
        if (ROUTED) arow = v ? (seg + mbase + lrow) : seg;
        else        arow = mbase + lrow;
    }
    const char* gA = (const char*)(Af + (size_t)arow * K) + hbA;

    const int bk  = tid >> 2;
    const int bnb = (tid & 3) * 64;
    uint32_t soB[4];
#pragma unroll
    for (int j = 0; j < 4; ++j)
        soB[j] = (uint32_t)bk * 256u + (((uint32_t)bnb + j * 16u) ^ (((uint32_t)bk & 7u) << 4));

    const size_t bexp = ROUTED ? (size_t)e * (size_t)K * (size_t)N : 0;
    const size_t brow = bexp + (size_t)bk * N + nbase;
    const char* gB = (const char*)(Bf + brow) + bnb;
    const size_t bstep = (size_t)KC * N * 2;

    const int nk = K / KC;

#define ISSUE_D(slot, kt)                                                       \
    do {                                                                        \
        uint32_t b_ = sb + (uint32_t)(slot) * STG;                              \
        size_t ak_ = (size_t)(kt) * 128;                                        \
        size_t bk_ = (size_t)(kt) * bstep;                                      \
        _Pragma("unroll")                                                       \
        for (int j_ = 0; j_ < 4; ++j_) {                                        \
            cp16(b_ + soA[j_],        gA + ak_ + j_ * 16);                      \
            cp16(b_ + OF_B + soB[j_], gB + bk_ + j_ * 16);                      \
        }                                                                       \
        CP_COMMIT();                                                            \
    } while (0)

    const int wm = (wid >> 2) * 64;
    const int wn = (wid & 3) * 32;

    uint32_t aOff[4];
#pragma unroll
    for (int mf = 0; mf < 4; ++mf)
        aOff[mf] = (uint32_t)(wm + mf * 16 + (lane & 15)) * 128u
                 + (uint32_t)((lane >> 4) * 16);
    uint32_t bB[2];
    {
        uint32_t r = lane & 7u, m = lane >> 3;
#pragma unroll
        for (int nf2 = 0; nf2 < 2; ++nf2) {
            uint32_t nb = (uint32_t)(wn + nf2 * 16 + (int)((m >> 1) * 8)) * 2u;
            bB[nf2] = ((m & 1u) * 8u + r) * 256u + (nb ^ (r << 4));
        }
    }

    float acc[4][4][4];
#pragma unroll
    for (int i = 0; i < 4; ++i)
#pragma unroll
        for (int j = 0; j < 4; ++j)
#pragma unroll
            for (int q = 0; q < 4; ++q) acc[i][j][q] = 0.f;

    ISSUE_D(0, 0);
    ISSUE_D(1, 1);

    for (int kt = 0; kt < nk; ++kt) {
        const int s = kt % 3;
        if (kt + 1 < nk) cp_wait<1>(); else cp_wait<0>();
        __syncthreads();
        if (kt + 2 < nk) ISSUE_D((kt + 2) % 3, kt + 2);

        const uint32_t stb = sb + (uint32_t)s * STG;
#pragma unroll
        for (int ks = 0; ks < 4; ++ks) {
            uint32_t a[4][4], b[2][4];
#pragma unroll
            for (int mf = 0; mf < 4; ++mf)
                ldsm4(a[mf], stb + swzA(aOff[mf] + ks * 32u));
#pragma unroll
            for (int nf2 = 0; nf2 < 2; ++nf2)
                ldsm4t(b[nf2], stb + OF_B + bB[nf2] + ks * 4096u);
#pragma unroll
            for (int mf = 0; mf < 4; ++mf)
#pragma unroll
                for (int nf = 0; nf < 4; ++nf)
                    mma_f16(acc[mf][nf], a[mf],
                            b[nf >> 1][(nf & 1) * 2], b[nf >> 1][(nf & 1) * 2 + 1]);
        }
    }
#undef ISSUE_D

    if (!ROUTED) {
#pragma unroll
        for (int mf = 0; mf < 4; ++mf) {
#pragma unroll
            for (int nf = 0; nf < 4; ++nf) {
                int r0 = mbase + wm + mf * 16 + (lane >> 2);
                int n0 = nbase + wn + nf * 8 + (lane & 3) * 2;
                float* c = acc[mf][nf];
                if (r0 < M)
                    *(float2*)&Cf[(size_t)r0 * N + n0] = make_float2(c[0], c[1]);
                if (r0 + 8 < M)
                    *(float2*)&Cf[(size_t)(r0 + 8) * N + n0] = make_float2(c[2], c[3]);
            }
        }
    } else {
        // fused combine: out[token] += slot_weight * acc
#pragma unroll
        for (int mf = 0; mf < 4; ++mf) {
#pragma unroll
            for (int h = 0; h < 2; ++h) {
                int r = mbase + wm + mf * 16 + (lane >> 2) + h * 8;
                if (r < M) {
                    int slot = seg + r;
                    int tok  = g_rowtok[slot];
                    float w  = g_slotw[slot];
                    float* orow = Cf + (size_t)tok * N;
#pragma unroll
                    for (int nf = 0; nf < 4; ++nf) {
                        int n0 = nbase + wn + nf * 8 + (lane & 3) * 2;
                        float* c = acc[mf][nf];
                        atomicAdd(&orow[n0],     w * c[h * 2 + 0]);
                        atomicAdd(&orow[n0 + 1], w * c[h * 2 + 1]);
                    }
                }
            }
        }
    }
}

// ---------------- launch -----------------------------------------------------
extern "C" void kernel_launch(void* const* d_in, const int* in_sizes, int n_in,
                              void* d_out, int out_size) {
    (void)in_sizes; (void)n_in; (void)out_size;
    const float* x      = (const float*)d_in[0];
    // d_in[1] router_w, d_in[2] router_b: dead inputs (RandomSTE forward = noise)
    const float* w_gate = (const float*)d_in[3];
    const float* w_up   = (const float*)d_in[4];
    const float* w_down = (const float*)d_in[5];
    const float* sg     = (const float*)d_in[6];
    const float* su     = (const float*)d_in[7];
    const float* sd     = (const float*)d_in[8];
    float* out = (float*)d_out;

    auto sym = [](const void* s) {
        void* p = nullptr;
        cudaGetSymbolAddress(&p, s);
        return p;
    };
    __half* xf  = (__half*)sym(g_xf);
    __half* sgf = (__half*)sym(g_sgf);
    __half* suf = (__half*)sym(g_suf);
    __half* sdf = (__half*)sym(g_sdf);
    __half* wgf = (__half*)sym(g_wgf);
    __half* wuf = (__half*)sym(g_wuf);
    __half* wdf = (__half*)sym(g_wdf);
    __half* hsf = (__half*)sym(g_hsf);
    __half* hrf = (__half*)sym(g_hrf);

    const int SM_F = 3 * 3 * (64 * 256);   // 147456
    const int SM_D = 3 * 2 * (64 * 256);   // 98304

    // One-time host-object setup; the capture call performs ZERO creations.
    static cudaStream_t s2 = nullptr, s3 = nullptr;
    static cudaEvent_t evRoot, evX, evWD, evSD, evR;
    if (s2 == nullptr) {
        cudaFuncSetAttribute((const void*)mma_fused<false, false>,
                             cudaFuncAttributeMaxDynamicSharedMemorySize, SM_F);
        cudaFuncSetAttribute((const void*)mma_fused<true, true>,
                             cudaFuncAttributeMaxDynamicSharedMemorySize, SM_F);
        cudaFuncSetAttribute((const void*)mma_down<false>,
                             cudaFuncAttributeMaxDynamicSharedMemorySize, SM_D);
        cudaFuncSetAttribute((const void*)mma_down<true>,
                             cudaFuncAttributeMaxDynamicSharedMemorySize, SM_D);
        cudaStreamCreateWithFlags(&s2, cudaStreamNonBlocking);
        cudaStreamCreateWithFlags(&s3, cudaStreamNonBlocking);
        cudaEventCreateWithFlags(&evRoot, cudaEventDisableTiming);
        cudaEventCreateWithFlags(&evX, cudaEventDisableTiming);
        cudaEventCreateWithFlags(&evWD, cudaEventDisableTiming);
        cudaEventCreateWithFlags(&evSD, cudaEventDisableTiming);
        cudaEventCreateWithFlags(&evR, cudaEventDisableTiming);
    }

    auto convGrid = [](size_t n) { return (unsigned)(n / (256 * 16)); };

    // ---- fork: every side stream joins the capture via evRoot BEFORE any work
    cudaEventRecord(evRoot, 0);
    cudaStreamWaitEvent(s2, evRoot, 0);
    cudaStreamWaitEvent(s3, evRoot, 0);

    // ---- legacy: x conversion (critical for all GEMM A-sides)
    conv_f16<<<convGrid((size_t)T_TOKENS * H_DIM), 256>>>(
        x, xf, (size_t)T_TOKENS * H_DIM / 16);
    cudaEventRecord(evX, 0);

    // ---- s2: routing + wg/wu conversions + routed fused GEMM
    zero_kernel<<<1, 32, 0, s2>>>();
    route_kernel<<<T_TOKENS / 256, 256, 0, s2>>>();
    scan_kernel<<<1, 1, 0, s2>>>();
    scatter_kernel<<<T_TOKENS / 256, 256, 0, s2>>>();
    conv_f16<<<convGrid((size_t)E_NUM * H_DIM * I_DIM), 256, 0, s2>>>(
        w_gate, wgf, (size_t)E_NUM * H_DIM * I_DIM / 16);
    conv_f16<<<convGrid((size_t)E_NUM * H_DIM * I_DIM), 256, 0, s2>>>(
        w_up, wuf, (size_t)E_NUM * H_DIM * I_DIM / 16);
    cudaStreamWaitEvent(s2, evX, 0);
    mma_fused<true, true>
        <<<dim3(I_DIM / 128, T_TOKENS / 128, E_NUM), 256, SM_F, s2>>>(
            xf, wgf, wuf, hrf, H_DIM, I_DIM, 0);

    // ---- s3: wd conversion (needed only by routed down)
    conv_f16<<<convGrid((size_t)E_NUM * I_DIM * H_DIM), 256, 0, s3>>>(
        w_down, wdf, (size_t)E_NUM * I_DIM * H_DIM / 16);
    cudaEventRecord(evWD, s3);

    // ---- legacy: shared path (convs + GEMMs); shared down overwrites out
    conv_f16<<<convGrid((size_t)H_DIM * SI_DIM), 256>>>(
        sg, sgf, (size_t)H_DIM * SI_DIM / 16);
    conv_f16<<<convGrid((size_t)H_DIM * SI_DIM), 256>>>(
        su, suf, (size_t)H_DIM * SI_DIM / 16);
    conv_f16<<<convGrid((size_t)SI_DIM * H_DIM), 256>>>(
        sd, sdf, (size_t)SI_DIM * H_DIM / 16);
    mma_fused<false, false>
        <<<dim3(SI_DIM / 128, T_TOKENS / 128, 1), 256, SM_F>>>(
            xf, sgf, suf, hsf, H_DIM, SI_DIM, T_TOKENS);
    mma_down<false>
        <<<dim3(H_DIM / 128, T_TOKENS / 128, 1), 256, SM_D>>>(
            hsf, sdf, out, SI_DIM, H_DIM, T_TOKENS);
    cudaEventRecord(evSD, 0);

    // ---- s2: routed down with fused combine (atomicAdd into out)
    cudaStreamWaitEvent(s2, evSD, 0);   // out must be fully written first
    cudaStreamWaitEvent(s2, evWD, 0);   // wd weights ready
    mma_down<true>
        <<<dim3(H_DIM / 128, T_TOKENS / 128, E_NUM), 256, SM_D, s2>>>(
            hrf, wdf, out, I_DIM, H_DIM, 0);
    cudaEventRecord(evR, s2);

    // ---- join on legacy stream
    cudaStreamWaitEvent(0, evR, 0);
}

// round 16
// speedup vs baseline: 1.0031x; 1.0031x over previous
#include <cuda_runtime.h>
#include <cuda_fp16.h>
#include <cstdint>

#define T_TOKENS 4096
#define H_DIM    2048
#define I_DIM    1408
#define E_NUM    16
#define SI_DIM   2816
#define SLOTS    8192   // T * TOP_K

// ---------------- scratch (device globals; no runtime allocation) ----------
__device__ int   g_cnt[E_NUM];
__device__ int   g_off[E_NUM];
__device__ int   g_cur[E_NUM];
__device__ int   g_eid[T_TOKENS * 2];
__device__ float g_wgt[T_TOKENS * 2];
__device__ int   g_slot[T_TOKENS * 2];
__device__ int   g_rowtok[SLOTS];

// fp16 operands (all natural layout; no transposes)
__device__ __half g_xf[T_TOKENS * H_DIM];
__device__ __half g_sgf[H_DIM * SI_DIM];
__device__ __half g_suf[H_DIM * SI_DIM];
__device__ __half g_sdf[SI_DIM * H_DIM];
__device__ __half g_wgf[E_NUM * H_DIM * I_DIM];
__device__ __half g_wuf[E_NUM * H_DIM * I_DIM];
__device__ __half g_wdf[E_NUM * I_DIM * H_DIM];
// intermediate activations
__device__ __half g_hsf[T_TOKENS * SI_DIM];
__device__ __half g_hrf[SLOTS * I_DIM];
__device__ float  g_Y[SLOTS * H_DIM];   // routed down output

// ---------------- threefry2x32 core (verified vs Random123 KAT) -------------
__device__ __forceinline__ uint32_t rotl32(uint32_t v, int r) {
    return (v << r) | (v >> (32 - r));
}

__device__ __forceinline__ void threefry2x32(uint32_t x0, uint32_t x1,
                                             uint32_t& o0, uint32_t& o1) {
    const uint32_t ks0 = 0u, ks1 = 42u, ks2 = 0u ^ 42u ^ 0x1BD11BDAu;
    x0 += ks0; x1 += ks1;
    x0 += x1; x1 = rotl32(x1, 13); x1 ^= x0;
    x0 += x1; x1 = rotl32(x1, 15); x1 ^= x0;
    x0 += x1; x1 = rotl32(x1, 26); x1 ^= x0;
    x0 += x1; x1 = rotl32(x1, 6);  x1 ^= x0;
    x0 += ks1; x1 += ks2 + 1u;
    x0 += x1; x1 = rotl32(x1, 17); x1 ^= x0;
    x0 += x1; x1 = rotl32(x1, 29); x1 ^= x0;
    x0 += x1; x1 = rotl32(x1, 16); x1 ^= x0;
    x0 += x1; x1 = rotl32(x1, 24); x1 ^= x0;
    x0 += ks2; x1 += ks0 + 2u;
    x0 += x1; x1 = rotl32(x1, 13); x1 ^= x0;
    x0 += x1; x1 = rotl32(x1, 15); x1 ^= x0;
    x0 += x1; x1 = rotl32(x1, 26); x1 ^= x0;
    x0 += x1; x1 = rotl32(x1, 6);  x1 ^= x0;
    x0 += ks0; x1 += ks1 + 3u;
    x0 += x1; x1 = rotl32(x1, 17); x1 ^= x0;
    x0 += x1; x1 = rotl32(x1, 29); x1 ^= x0;
    x0 += x1; x1 = rotl32(x1, 16); x1 ^= x0;
    x0 += x1; x1 = rotl32(x1, 24); x1 ^= x0;
    x0 += ks1; x1 += ks2 + 4u;
    x0 += x1; x1 = rotl32(x1, 13); x1 ^= x0;
    x0 += x1; x1 = rotl32(x1, 15); x1 ^= x0;
    x0 += x1; x1 = rotl32(x1, 26); x1 ^= x0;
    x0 += x1; x1 = rotl32(x1, 6);  x1 ^= x0;
    x0 += ks2; x1 += ks0 + 5u;
    o0 = x0; o1 = x1;
}

__device__ __forceinline__ float erfinv_xla(float x) {
    float w = -log1pf(-x * x);
    float p;
    if (w < 5.0f) {
        w -= 2.5f;
        p = 2.81022636e-08f;
        p = fmaf(p, w, 3.43273939e-07f);
        p = fmaf(p, w, -3.5233877e-06f);
        p = fmaf(p, w, -4.39150654e-06f);
        p = fmaf(p, w, 0.00021858087f);
        p = fmaf(p, w, -0.00125372503f);
        p = fmaf(p, w, -0.00417768164f);
        p = fmaf(p, w, 0.246640727f);
        p = fmaf(p, w, 1.50140941f);
    } else {
        w = sqrtf(w) - 3.0f;
        p = -0.000200214257f;
        p = fmaf(p, w, 0.000100950558f);
        p = fmaf(p, w, 0.00134934322f);
        p = fmaf(p, w, -0.00367342844f);
        p = fmaf(p, w, 0.00573950773f);
        p = fmaf(p, w, -0.0076224613f);
        p = fmaf(p, w, 0.00943887047f);
        p = fmaf(p, w, 1.00167406f);
        p = fmaf(p, w, 2.83297682f);
    }
    return p * x;
}

// ---------------- routing kernels ------------------------------------------
__global__ void zero_kernel() {
    if (threadIdx.x < E_NUM) g_cnt[threadIdx.x] = 0;
}

__global__ void route_kernel() {
    int t = blockIdx.x * blockDim.x + threadIdx.x;
    if (t >= T_TOKENS) return;
    float s[E_NUM];
#pragma unroll
    for (int e = 0; e < E_NUM; ++e) {
        uint32_t i = (uint32_t)t * E_NUM + (uint32_t)e;
        uint32_t o0, o1;
        threefry2x32(0u, i, o0, o1);
        uint32_t bits = o0 ^ o1;
        float u01 = __uint_as_float((bits >> 9) | 0x3f800000u) - 1.0f;
        float u = fmaf(u01, 2.0f, -0.99999994f);
        u = fmaxf(-0.99999994f, u);
        float nz = 1.4142135381698608f * erfinv_xla(u);
        s[e] = 1.0f / (1.0f + expf(-nz));
    }
    int b0 = 0;
#pragma unroll
    for (int e = 1; e < E_NUM; ++e) if (s[e] > s[b0]) b0 = e;
    int b1 = (b0 == 0) ? 1 : 0;
#pragma unroll
    for (int e = 0; e < E_NUM; ++e) if (e != b0 && s[e] > s[b1]) b1 = e;
    float sum = s[b0] + s[b1] + 1e-8f;
    g_eid[2 * t + 0] = b0;
    g_eid[2 * t + 1] = b1;
    g_wgt[2 * t + 0] = s[b0] / sum;
    g_wgt[2 * t + 1] = s[b1] / sum;
    atomicAdd(&g_cnt[b0], 1);
    atomicAdd(&g_cnt[b1], 1);
}

__global__ void scan_kernel() {
    int a = 0;
    for (int e = 0; e < E_NUM; ++e) { g_off[e] = a; g_cur[e] = a; a += g_cnt[e]; }
}

__global__ void scatter_kernel() {
    int t = blockIdx.x * blockDim.x + threadIdx.x;
    if (t >= T_TOKENS) return;
#pragma unroll
    for (int k = 0; k < 2; ++k) {
        int e = g_eid[2 * t + k];
        int sidx = atomicAdd(&g_cur[e], 1);
        g_slot[2 * t + k] = sidx;
        g_rowtok[sidx] = t;
    }
}

// ---------------- grid-stride streaming conversion (MLP=4) ------------------
__global__ void conv_f16(const float* __restrict__ src,
                         __half* __restrict__ dst, size_t n16) {
    size_t g = (size_t)blockIdx.x * blockDim.x + threadIdx.x;
    size_t gs = (size_t)gridDim.x * blockDim.x;
    for (size_t c = g; c < n16; c += gs) {
        const float4* s4 = (const float4*)(src + c * 16);
        float4 v[4];
#pragma unroll
        for (int j = 0; j < 4; ++j) v[j] = s4[j];
        uint2* d4 = (uint2*)(dst + c * 16);
#pragma unroll
        for (int j = 0; j < 4; ++j) {
            __half f[4];
            f[0] = __float2half_rn(v[j].x);
            f[1] = __float2half_rn(v[j].y);
            f[2] = __float2half_rn(v[j].z);
            f[3] = __float2half_rn(v[j].w);
            d4[j] = *(uint2*)f;
        }
    }
}

// ---------------- warp-MMA helpers ------------------------------------------
__device__ __forceinline__ uint32_t smem_u32(const void* p) {
    uint32_t a;
    asm("{ .reg .u64 t; cvta.to.shared.u64 t, %1; cvt.u32.u64 %0, t; }"
        : "=r"(a) : "l"(p));
    return a;
}

__device__ __forceinline__ void cp16(uint32_t s, const void* g) {
    asm volatile("cp.async.cg.shared.global [%0], [%1], 16;"
                 :: "r"(s), "l"(g) : "memory");
}
#define CP_COMMIT() asm volatile("cp.async.commit_group;" ::: "memory")
template <int N>
__device__ __forceinline__ void cp_wait() {
    asm volatile("cp.async.wait_group %0;" :: "n"(N) : "memory");
}

__device__ __forceinline__ void ldsm4(uint32_t* r, uint32_t a) {
    asm volatile("ldmatrix.sync.aligned.m8n8.x4.shared.b16 {%0,%1,%2,%3}, [%4];"
                 : "=r"(r[0]), "=r"(r[1]), "=r"(r[2]), "=r"(r[3]) : "r"(a));
}
__device__ __forceinline__ void ldsm4t(uint32_t* r, uint32_t a) {
    asm volatile("ldmatrix.sync.aligned.m8n8.x4.trans.shared.b16 {%0,%1,%2,%3}, [%4];"
                 : "=r"(r[0]), "=r"(r[1]), "=r"(r[2]), "=r"(r[3]) : "r"(a));
}

__device__ __forceinline__ void mma_f16(float* c, const uint32_t* a,
                                        uint32_t b0, uint32_t b1) {
    asm volatile(
        "mma.sync.aligned.m16n8k16.row.col.f32.f16.f16.f32 "
        "{%0,%1,%2,%3}, {%4,%5,%6,%7}, {%8,%9}, {%0,%1,%2,%3};"
        : "+f"(c[0]), "+f"(c[1]), "+f"(c[2]), "+f"(c[3])
        : "r"(a[0]), "r"(a[1]), "r"(a[2]), "r"(a[3]), "r"(b0), "r"(b1));
}

__device__ __forceinline__ float swiglu_f(float g, float u) {
    return (g / (1.0f + expf(-g))) * u;
}

// A-tile swizzle (128B rows)
__device__ __forceinline__ uint32_t swzA(uint32_t off) {
    return off ^ ((off >> 3) & 0x70u);
}

// =============================================================================
// FUSED gate+up GEMM (fp16 single-pass). A k-major [M][K]; B natural [K][N]
// via ldmatrix.trans. Epilogue -> fp16 swiglu acts.
// CTA 128x128, KC=64, 3 stages (48KB/stage), 8 warps (2x4), warp tile 64x32.
// =============================================================================
template <bool ROUTED, bool GATHER>
__global__ void __launch_bounds__(256, 1)
mma_fused(const __half* __restrict__ Af,
          const __half* __restrict__ B1f, const __half* __restrict__ B2f,
          __half* __restrict__ Ohf, int K, int N, int fixedM)
{
    constexpr int KC   = 64;
    constexpr int TILE = KC * 256;     // 16 KB
    constexpr int STG  = 3 * TILE;     // 48 KB
    constexpr int OF_B1 = TILE;
    constexpr int OF_B2 = 2 * TILE;

    extern __shared__ char smem[];
    const int tid  = threadIdx.x;
    const int wid  = tid >> 5;
    const int lane = tid & 31;

    const int e = blockIdx.z;
    int M, seg;
    if (ROUTED) { M = g_cnt[e]; seg = g_off[e]; }
    else        { M = fixedM;   seg = 0; }
    const int mbase = blockIdx.y * 128;
    if (mbase >= M) return;
    const int nbase = blockIdx.x * 128;

    const uint32_t sb = smem_u32(smem);

    const int lrow = tid >> 1;
    const int hbA  = (tid & 1) * 64;
    uint32_t soA[4];
#pragma unroll
    for (int j = 0; j < 4; ++j)
        soA[j] = swzA((uint32_t)lrow * 128u + (uint32_t)hbA + j * 16u);

    int arow;
    {
        bool v = (mbase + lrow) < M;
        if (ROUTED) {
            int slot = seg + mbase + lrow;
            if (GATHER) arow = v ? g_rowtok[slot] : 0;
            else        arow = v ? slot : seg;
        } else arow = mbase + lrow;
    }
    const char* gA = (const char*)(Af + (size_t)arow * K) + hbA;

    const int bk  = tid >> 2;
    const int bnb = (tid & 3) * 64;
    uint32_t soB[4];
#pragma unroll
    for (int j = 0; j < 4; ++j)
        soB[j] = (uint32_t)bk * 256u + (((uint32_t)bnb + j * 16u) ^ (((uint32_t)bk & 7u) << 4));

    const size_t bexp = ROUTED ? (size_t)e * (size_t)K * (size_t)N : 0;
    const size_t brow = bexp + (size_t)bk * N + nbase;
    const char* gB1 = (const char*)(B1f + brow) + bnb;
    const char* gB2 = (const char*)(B2f + brow) + bnb;
    const size_t bstep = (size_t)KC * N * 2;

    const int nk = K / KC;

#define ISSUE_F(slot, kt)                                                       \
    do {                                                                        \
        uint32_t b_ = sb + (uint32_t)(slot) * STG;                              \
        size_t ak_ = (size_t)(kt) * 128;                                        \
        size_t bk_ = (size_t)(kt) * bstep;                                      \
        _Pragma("unroll")                                                       \
        for (int j_ = 0; j_ < 4; ++j_) {                                        \
            cp16(b_ + soA[j_],         gA  + ak_ + j_ * 16);                    \
            cp16(b_ + OF_B1 + soB[j_], gB1 + bk_ + j_ * 16);                    \
            cp16(b_ + OF_B2 + soB[j_], gB2 + bk_ + j_ * 16);                    \
        }                                                                       \
        CP_COMMIT();                                                            \
    } while (0)

    const int wm = (wid >> 2) * 64;
    const int wn = (wid & 3) * 32;

    uint32_t aOff[4];
#pragma unroll
    for (int mf = 0; mf < 4; ++mf)
        aOff[mf] = (uint32_t)(wm + mf * 16 + (lane & 15)) * 128u
                 + (uint32_t)((lane >> 4) * 16);
    uint32_t bB[2];
    {
        uint32_t r = lane & 7u, m = lane >> 3;
#pragma unroll
        for (int nf2 = 0; nf2 < 2; ++nf2) {
            uint32_t nb = (uint32_t)(wn + nf2 * 16 + (int)((m >> 1) * 8)) * 2u;
            bB[nf2] = ((m & 1u) * 8u + r) * 256u + (nb ^ (r << 4));
        }
    }

    float accG[4][4][4], accU[4][4][4];
#pragma unroll
    for (int i = 0; i < 4; ++i)
#pragma unroll
        for (int j = 0; j < 4; ++j)
#pragma unroll
            for (int q = 0; q < 4; ++q) { accG[i][j][q] = 0.f; accU[i][j][q] = 0.f; }

    ISSUE_F(0, 0);
    ISSUE_F(1, 1);

    for (int kt = 0; kt < nk; ++kt) {
        const int s = kt % 3;
        if (kt + 1 < nk) cp_wait<1>(); else cp_wait<0>();
        __syncthreads();
        if (kt + 2 < nk) ISSUE_F((kt + 2) % 3, kt + 2);

        const uint32_t stb = sb + (uint32_t)s * STG;
#pragma unroll
        for (int ks = 0; ks < 4; ++ks) {
            uint32_t a[4][4], b1[2][4], b2[2][4];
#pragma unroll
            for (int mf = 0; mf < 4; ++mf)
                ldsm4(a[mf], stb + swzA(aOff[mf] + ks * 32u));
#pragma unroll
            for (int nf2 = 0; nf2 < 2; ++nf2) {
                uint32_t off = bB[nf2] + ks * 4096u;
                ldsm4t(b1[nf2], stb + OF_B1 + off);
                ldsm4t(b2[nf2], stb + OF_B2 + off);
            }
#pragma unroll
            for (int mf = 0; mf < 4; ++mf)
#pragma unroll
                for (int nf = 0; nf < 4; ++nf)
                    mma_f16(accG[mf][nf], a[mf],
                            b1[nf >> 1][(nf & 1) * 2], b1[nf >> 1][(nf & 1) * 2 + 1]);
#pragma unroll
            for (int mf = 0; mf < 4; ++mf)
#pragma unroll
                for (int nf = 0; nf < 4; ++nf)
                    mma_f16(accU[mf][nf], a[mf],
                            b2[nf >> 1][(nf & 1) * 2], b2[nf >> 1][(nf & 1) * 2 + 1]);
        }
    }
#undef ISSUE_F

    const size_t rowoff = ROUTED ? (size_t)seg : 0;
#pragma unroll
    for (int mf = 0; mf < 4; ++mf) {
#pragma unroll
        for (int nf = 0; nf < 4; ++nf) {
            int r0 = mbase + wm + mf * 16 + (lane >> 2);
            int n0 = nbase + wn + nf * 8 + (lane & 3) * 2;
            float* cg = accG[mf][nf];
            float* cu = accU[mf][nf];
#pragma unroll
            for (int h = 0; h < 2; ++h) {
                int r = r0 + h * 8;
                if (r < M) {
                    size_t idx = (rowoff + r) * (size_t)N + n0;
                    float a0 = swiglu_f(cg[h * 2 + 0], cu[h * 2 + 0]);
                    float a1 = swiglu_f(cg[h * 2 + 1], cu[h * 2 + 1]);
                    __half2 hp = __floats2half2_rn(a0, a1);
                    *(uint32_t*)&Ohf[idx] = *reinterpret_cast<uint32_t*>(&hp);
                }
            }
        }
    }
}

// =============================================================================
// DOWN GEMM (fp16 single-pass). A k-major; B natural [K][N]; out fp32.
// CTA 128x128, KC=64, 3 stages (32KB/stage).
// =============================================================================
template <bool ROUTED>
__global__ void __launch_bounds__(256, 1)
mma_down(const __half* __restrict__ Af, const __half* __restrict__ Bf,
         float* __restrict__ Cf, int K, int N, int fixedM)
{
    constexpr int KC   = 64;
    constexpr int TILE = KC * 256;
    constexpr int STG  = 2 * TILE;     // 32 KB
    constexpr int OF_B = TILE;

    extern __shared__ char smem[];
    const int tid  = threadIdx.x;
    const int wid  = tid >> 5;
    const int lane = tid & 31;

    const int e = blockIdx.z;
    int M, seg;
    if (ROUTED) { M = g_cnt[e]; seg = g_off[e]; }
    else        { M = fixedM;   seg = 0; }
    const int mbase = blockIdx.y * 128;
    if (mbase >= M) return;
    const int nbase = blockIdx.x * 128;

    const uint32_t sb = smem_u32(smem);

    const int lrow = tid >> 1;
    const int hbA  = (tid & 1) * 64;
    uint32_t soA[4];
#pragma unroll
    for (int j = 0; j < 4; ++j)
        soA[j] = swzA((uint32_t)lrow * 128u + (uint32_t)hbA + j * 16u);

    int arow;
    {
        bool v = (mbase + lrow) < M;
        if (ROUTED) arow = v ? (seg + mbase + lrow) : seg;
        else        arow = mbase + lrow;
    }
    const char* gA = (const char*)(Af + (size_t)arow * K) + hbA;

    const int bk  = tid >> 2;
    const int bnb = (tid & 3) * 64;
    uint32_t soB[4];
#pragma unroll
    for (int j = 0; j < 4; ++j)
        soB[j] = (uint32_t)bk * 256u + (((uint32_t)bnb + j * 16u) ^ (((uint32_t)bk & 7u) << 4));

    const size_t bexp = ROUTED ? (size_t)e * (size_t)K * (size_t)N : 0;
    const size_t brow = bexp + (size_t)bk * N + nbase;
    const char* gB = (const char*)(Bf + brow) + bnb;
    const size_t bstep = (size_t)KC * N * 2;

    const int nk = K / KC;

#define ISSUE_D(slot, kt)                                                       \
    do {                                                                        \
        uint32_t b_ = sb + (uint32_t)(slot) * STG;                              \
        size_t ak_ = (size_t)(kt) * 128;                                        \
        size_t bk_ = (size_t)(kt) * bstep;                                      \
        _Pragma("unroll")                                                       \
        for (int j_ = 0; j_ < 4; ++j_) {                                        \
            cp16(b_ + soA[j_],        gA + ak_ + j_ * 16);                      \
            cp16(b_ + OF_B + soB[j_], gB + bk_ + j_ * 16);                      \
        }                                                                       \
        CP_COMMIT();                                                            \
    } while (0)

    const int wm = (wid >> 2) * 64;
    const int wn = (wid & 3) * 32;

    uint32_t aOff[4];
#pragma unroll
    for (int mf = 0; mf < 4; ++mf)
        aOff[mf] = (uint32_t)(wm + mf * 16 + (lane & 15)) * 128u
                 + (uint32_t)((lane >> 4) * 16);
    uint32_t bB[2];
    {
        uint32_t r = lane & 7u, m = lane >> 3;
#pragma unroll
        for (int nf2 = 0; nf2 < 2; ++nf2) {
            uint32_t nb = (uint32_t)(wn + nf2 * 16 + (int)((m >> 1) * 8)) * 2u;
            bB[nf2] = ((m & 1u) * 8u + r) * 256u + (nb ^ (r << 4));
        }
    }

    float acc[4][4][4];
#pragma unroll
    for (int i = 0; i < 4; ++i)
#pragma unroll
        for (int j = 0; j < 4; ++j)
#pragma unroll
            for (int q = 0; q < 4; ++q) acc[i][j][q] = 0.f;

    ISSUE_D(0, 0);
    ISSUE_D(1, 1);

    for (int kt = 0; kt < nk; ++kt) {
        const int s = kt % 3;
        if (kt + 1 < nk) cp_wait<1>(); else cp_wait<0>();
        __syncthreads();
        if (kt + 2 < nk) ISSUE_D((kt + 2) % 3, kt + 2);

        const uint32_t stb = sb + (uint32_t)s * STG;
#pragma unroll
        for (int ks = 0; ks < 4; ++ks) {
            uint32_t a[4][4], b[2][4];
#pragma unroll
            for (int mf = 0; mf < 4; ++mf)
                ldsm4(a[mf], stb + swzA(aOff[mf] + ks * 32u));
#pragma unroll
            for (int nf2 = 0; nf2 < 2; ++nf2)
                ldsm4t(b[nf2], stb + OF_B + bB[nf2] + ks * 4096u);
#pragma unroll
            for (int mf = 0; mf < 4; ++mf)
#pragma unroll
                for (int nf = 0; nf < 4; ++nf)
                    mma_f16(acc[mf][nf], a[mf],
                            b[nf >> 1][(nf & 1) * 2], b[nf >> 1][(nf & 1) * 2 + 1]);
        }
    }
#undef ISSUE_D

    const size_t rowoff = ROUTED ? (size_t)seg : 0;
#pragma unroll
    for (int mf = 0; mf < 4; ++mf) {
#pragma unroll
        for (int nf = 0; nf < 4; ++nf) {
            int r0 = mbase + wm + mf * 16 + (lane >> 2);
            int n0 = nbase + wn + nf * 8 + (lane & 3) * 2;
            float* c = acc[mf][nf];
            if (r0 < M)
                *(float2*)&Cf[(rowoff + r0) * (size_t)N + n0] = make_float2(c[0], c[1]);
            if (r0 + 8 < M)
                *(float2*)&Cf[(rowoff + r0 + 8) * (size_t)N + n0] = make_float2(c[2], c[3]);
        }
    }
}

// ---------------- combine: out += w0*Y[slot0] + w1*Y[slot1] ------------------
__global__ void combine_kernel(float* __restrict__ out) {
    int t = blockIdx.y;
    int c = (blockIdx.x * blockDim.x + threadIdx.x) * 4;
    int s0 = g_slot[2 * t + 0], s1 = g_slot[2 * t + 1];
    float w0 = g_wgt[2 * t + 0], w1 = g_wgt[2 * t + 1];
    const float4 y0 = *(const float4*)&g_Y[(size_t)s0 * H_DIM + c];
    const float4 y1 = *(const float4*)&g_Y[(size_t)s1 * H_DIM + c];
    float4 o = *(float4*)&out[(size_t)t * H_DIM + c];
    o.x += w0 * y0.x + w1 * y1.x;
    o.y += w0 * y0.y + w1 * y1.y;
    o.z += w0 * y0.z + w1 * y1.z;
    o.w += w0 * y0.w + w1 * y1.w;
    *(float4*)&out[(size_t)t * H_DIM + c] = o;
}

// ---------------- launch -----------------------------------------------------
extern "C" void kernel_launch(void* const* d_in, const int* in_sizes, int n_in,
                              void* d_out, int out_size) {
    (void)in_sizes; (void)n_in; (void)out_size;
    const float* x      = (const float*)d_in[0];
    // d_in[1] router_w, d_in[2] router_b: dead inputs (RandomSTE forward = noise)
    const float* w_gate = (const float*)d_in[3];
    const float* w_up   = (const float*)d_in[4];
    const float* w_down = (const float*)d_in[5];
    const float* sg     = (const float*)d_in[6];
    const float* su     = (const float*)d_in[7];
    const float* sd     = (const float*)d_in[8];
    float* out = (float*)d_out;

    auto sym = [](const void* s) {
        void* p = nullptr;
        cudaGetSymbolAddress(&p, s);
        return p;
    };
    __half* xf  = (__half*)sym(g_xf);
    __half* sgf = (__half*)sym(g_sgf);
    __half* suf = (__half*)sym(g_suf);
    __half* sdf = (__half*)sym(g_sdf);
    __half* wgf = (__half*)sym(g_wgf);
    __half* wuf = (__half*)sym(g_wuf);
    __half* wdf = (__half*)sym(g_wdf);
    __half* hsf = (__half*)sym(g_hsf);
    __half* hrf = (__half*)sym(g_hrf);
    float*  Yp  = (float*)sym(g_Y);

    const int SM_F = 3 * 3 * (64 * 256);   // 147456
    const int SM_D = 3 * 2 * (64 * 256);   // 98304

    // One-time host-object setup; the capture call performs ZERO creations.
    static cudaStream_t s2 = nullptr, s3 = nullptr;
    static cudaEvent_t evRoot, evX, evWD, evR;
    if (s2 == nullptr) {
        cudaFuncSetAttribute((const void*)mma_fused<false, false>,
                             cudaFuncAttributeMaxDynamicSharedMemorySize, SM_F);
        cudaFuncSetAttribute((const void*)mma_fused<true, true>,
                             cudaFuncAttributeMaxDynamicSharedMemorySize, SM_F);
        cudaFuncSetAttribute((const void*)mma_down<false>,
                             cudaFuncAttributeMaxDynamicSharedMemorySize, SM_D);
        cudaFuncSetAttribute((const void*)mma_down<true>,
                             cudaFuncAttributeMaxDynamicSharedMemorySize, SM_D);
        cudaStreamCreateWithFlags(&s2, cudaStreamNonBlocking);
        cudaStreamCreateWithFlags(&s3, cudaStreamNonBlocking);
        cudaEventCreateWithFlags(&evRoot, cudaEventDisableTiming);
        cudaEventCreateWithFlags(&evX, cudaEventDisableTiming);
        cudaEventCreateWithFlags(&evWD, cudaEventDisableTiming);
        cudaEventCreateWithFlags(&evR, cudaEventDisableTiming);
    }

    auto convGrid = [](size_t n) { return (unsigned)(n / (256 * 16)); };

    // routed grid y: 12 blocks = 1536 rows/expert (counts are deterministic,
    // mean 512, sigma ~22 -> enormous margin)
    const int YRT = 12;

    // ---- fork: side streams join the capture via evRoot BEFORE any work
    cudaEventRecord(evRoot, 0);
    cudaStreamWaitEvent(s2, evRoot, 0);
    cudaStreamWaitEvent(s3, evRoot, 0);

    // ---- legacy: x conversion (critical for all GEMM A-sides)
    conv_f16<<<convGrid((size_t)T_TOKENS * H_DIM), 256>>>(
        x, xf, (size_t)T_TOKENS * H_DIM / 16);
    cudaEventRecord(evX, 0);

    // ---- s3: wd conversion (only needed by routed down)
    conv_f16<<<convGrid((size_t)E_NUM * I_DIM * H_DIM), 256, 0, s3>>>(
        w_down, wdf, (size_t)E_NUM * I_DIM * H_DIM / 16);
    cudaEventRecord(evWD, s3);

    // ---- s2: routing + wg/wu conversions + routed GEMMs
    zero_kernel<<<1, 32, 0, s2>>>();
    route_kernel<<<T_TOKENS / 256, 256, 0, s2>>>();
    scan_kernel<<<1, 1, 0, s2>>>();
    scatter_kernel<<<T_TOKENS / 256, 256, 0, s2>>>();
    conv_f16<<<convGrid((size_t)E_NUM * H_DIM * I_DIM), 256, 0, s2>>>(
        w_gate, wgf, (size_t)E_NUM * H_DIM * I_DIM / 16);
    conv_f16<<<convGrid((size_t)E_NUM * H_DIM * I_DIM), 256, 0, s2>>>(
        w_up, wuf, (size_t)E_NUM * H_DIM * I_DIM / 16);
    cudaStreamWaitEvent(s2, evX, 0);
    mma_fused<true, true>
        <<<dim3(I_DIM / 128, YRT, E_NUM), 256, SM_F, s2>>>(
            xf, wgf, wuf, hrf, H_DIM, I_DIM, 0);
    cudaStreamWaitEvent(s2, evWD, 0);
    mma_down<true>
        <<<dim3(H_DIM / 128, YRT, E_NUM), 256, SM_D, s2>>>(
            hrf, wdf, Yp, I_DIM, H_DIM, 0);
    cudaEventRecord(evR, s2);

    // ---- legacy: shared path (convs + GEMMs); shared down overwrites out
    conv_f16<<<convGrid((size_t)H_DIM * SI_DIM), 256>>>(
        sg, sgf, (size_t)H_DIM * SI_DIM / 16);
    conv_f16<<<convGrid((size_t)H_DIM * SI_DIM), 256>>>(
        su, suf, (size_t)H_DIM * SI_DIM / 16);
    conv_f16<<<convGrid((size_t)SI_DIM * H_DIM), 256>>>(
        sd, sdf, (size_t)SI_DIM * H_DIM / 16);
    mma_fused<false, false>
        <<<dim3(SI_DIM / 128, T_TOKENS / 128, 1), 256, SM_F>>>(
            xf, sgf, suf, hsf, H_DIM, SI_DIM, T_TOKENS);
    mma_down<false>
        <<<dim3(H_DIM / 128, T_TOKENS / 128, 1), 256, SM_D>>>(
            hsf, sdf, out, SI_DIM, H_DIM, T_TOKENS);

    // ---- join: combine needs routed Y (s2) and shared out (legacy)
    cudaStreamWaitEvent(0, evR, 0);
    combine_kernel<<<dim3(H_DIM / 1024, T_TOKENS), 256>>>(out);
}

// round 17
// speedup vs baseline: 1.1522x; 1.1486x over previous
#include <cuda_runtime.h>
#include <cuda_fp16.h>
#include <cstdint>

#define T_TOKENS 4096
#define H_DIM    2048
#define I_DIM    1408
#define E_NUM    16
#define SI_DIM   2816
#define SLOTS    8192   // T * TOP_K

// ---------------- scratch (device globals; no runtime allocation) ----------
__device__ int   g_cnt[E_NUM];
__device__ int   g_off[E_NUM];
__device__ int   g_cur[E_NUM];
__device__ int   g_eid[T_TOKENS * 2];
__device__ float g_wgt[T_TOKENS * 2];
__device__ int   g_slot[T_TOKENS * 2];
__device__ int   g_rowtok[SLOTS];

// fp16 operands (all natural layout; no transposes)
__device__ __half g_xf[T_TOKENS * H_DIM];
__device__ __half g_sgf[H_DIM * SI_DIM];
__device__ __half g_suf[H_DIM * SI_DIM];
__device__ __half g_sdf[SI_DIM * H_DIM];
__device__ __half g_wgf[E_NUM * H_DIM * I_DIM];
__device__ __half g_wuf[E_NUM * H_DIM * I_DIM];
__device__ __half g_wdf[E_NUM * I_DIM * H_DIM];
// intermediate activations
__device__ __half g_hsf[T_TOKENS * SI_DIM];
__device__ __half g_hrf[SLOTS * I_DIM];
__device__ float  g_Y[SLOTS * H_DIM];   // routed down output

// ---------------- threefry2x32 core (verified vs Random123 KAT) -------------
__device__ __forceinline__ uint32_t rotl32(uint32_t v, int r) {
    return (v << r) | (v >> (32 - r));
}

__device__ __forceinline__ void threefry2x32(uint32_t x0, uint32_t x1,
                                             uint32_t& o0, uint32_t& o1) {
    const uint32_t ks0 = 0u, ks1 = 42u, ks2 = 0u ^ 42u ^ 0x1BD11BDAu;
    x0 += ks0; x1 += ks1;
    x0 += x1; x1 = rotl32(x1, 13); x1 ^= x0;
    x0 += x1; x1 = rotl32(x1, 15); x1 ^= x0;
    x0 += x1; x1 = rotl32(x1, 26); x1 ^= x0;
    x0 += x1; x1 = rotl32(x1, 6);  x1 ^= x0;
    x0 += ks1; x1 += ks2 + 1u;
    x0 += x1; x1 = rotl32(x1, 17); x1 ^= x0;
    x0 += x1; x1 = rotl32(x1, 29); x1 ^= x0;
    x0 += x1; x1 = rotl32(x1, 16); x1 ^= x0;
    x0 += x1; x1 = rotl32(x1, 24); x1 ^= x0;
    x0 += ks2; x1 += ks0 + 2u;
    x0 += x1; x1 = rotl32(x1, 13); x1 ^= x0;
    x0 += x1; x1 = rotl32(x1, 15); x1 ^= x0;
    x0 += x1; x1 = rotl32(x1, 26); x1 ^= x0;
    x0 += x1; x1 = rotl32(x1, 6);  x1 ^= x0;
    x0 += ks0; x1 += ks1 + 3u;
    x0 += x1; x1 = rotl32(x1, 17); x1 ^= x0;
    x0 += x1; x1 = rotl32(x1, 29); x1 ^= x0;
    x0 += x1; x1 = rotl32(x1, 16); x1 ^= x0;
    x0 += x1; x1 = rotl32(x1, 24); x1 ^= x0;
    x0 += ks1; x1 += ks2 + 4u;
    x0 += x1; x1 = rotl32(x1, 13); x1 ^= x0;
    x0 += x1; x1 = rotl32(x1, 15); x1 ^= x0;
    x0 += x1; x1 = rotl32(x1, 26); x1 ^= x0;
    x0 += x1; x1 = rotl32(x1, 6);  x1 ^= x0;
    x0 += ks2; x1 += ks0 + 5u;
    o0 = x0; o1 = x1;
}

__device__ __forceinline__ float erfinv_xla(float x) {
    float w = -log1pf(-x * x);
    float p;
    if (w < 5.0f) {
        w -= 2.5f;
        p = 2.81022636e-08f;
        p = fmaf(p, w, 3.43273939e-07f);
        p = fmaf(p, w, -3.5233877e-06f);
        p = fmaf(p, w, -4.39150654e-06f);
        p = fmaf(p, w, 0.00021858087f);
        p = fmaf(p, w, -0.00125372503f);
        p = fmaf(p, w, -0.00417768164f);
        p = fmaf(p, w, 0.246640727f);
        p = fmaf(p, w, 1.50140941f);
    } else {
        w = sqrtf(w) - 3.0f;
        p = -0.000200214257f;
        p = fmaf(p, w, 0.000100950558f);
        p = fmaf(p, w, 0.00134934322f);
        p = fmaf(p, w, -0.00367342844f);
        p = fmaf(p, w, 0.00573950773f);
        p = fmaf(p, w, -0.0076224613f);
        p = fmaf(p, w, 0.00943887047f);
        p = fmaf(p, w, 1.00167406f);
        p = fmaf(p, w, 2.83297682f);
    }
    return p * x;
}

// ---------------- routing kernels ------------------------------------------
__global__ void zero_kernel() {
    if (threadIdx.x < E_NUM) g_cnt[threadIdx.x] = 0;
}

__global__ void route_kernel() {
    int t = blockIdx.x * blockDim.x + threadIdx.x;
    if (t >= T_TOKENS) return;
    float s[E_NUM];
#pragma unroll
    for (int e = 0; e < E_NUM; ++e) {
        uint32_t i = (uint32_t)t * E_NUM + (uint32_t)e;
        uint32_t o0, o1;
        threefry2x32(0u, i, o0, o1);
        uint32_t bits = o0 ^ o1;
        float u01 = __uint_as_float((bits >> 9) | 0x3f800000u) - 1.0f;
        float u = fmaf(u01, 2.0f, -0.99999994f);
        u = fmaxf(-0.99999994f, u);
        float nz = 1.4142135381698608f * erfinv_xla(u);
        s[e] = 1.0f / (1.0f + expf(-nz));
    }
    int b0 = 0;
#pragma unroll
    for (int e = 1; e < E_NUM; ++e) if (s[e] > s[b0]) b0 = e;
    int b1 = (b0 == 0) ? 1 : 0;
#pragma unroll
    for (int e = 0; e < E_NUM; ++e) if (e != b0 && s[e] > s[b1]) b1 = e;
    float sum = s[b0] + s[b1] + 1e-8f;
    g_eid[2 * t + 0] = b0;
    g_eid[2 * t + 1] = b1;
    g_wgt[2 * t + 0] = s[b0] / sum;
    g_wgt[2 * t + 1] = s[b1] / sum;
    atomicAdd(&g_cnt[b0], 1);
    atomicAdd(&g_cnt[b1], 1);
}

__global__ void scan_kernel() {
    int a = 0;
    for (int e = 0; e < E_NUM; ++e) { g_off[e] = a; g_cur[e] = a; a += g_cnt[e]; }
}

__global__ void scatter_kernel() {
    int t = blockIdx.x * blockDim.x + threadIdx.x;
    if (t >= T_TOKENS) return;
#pragma unroll
    for (int k = 0; k < 2; ++k) {
        int e = g_eid[2 * t + k];
        int sidx = atomicAdd(&g_cur[e], 1);
        g_slot[2 * t + k] = sidx;
        g_rowtok[sidx] = t;
    }
}

// ---------------- grid-stride streaming conversion (MLP=4) ------------------
__global__ void conv_f16(const float* __restrict__ src,
                         __half* __restrict__ dst, size_t n16) {
    size_t g = (size_t)blockIdx.x * blockDim.x + threadIdx.x;
    size_t gs = (size_t)gridDim.x * blockDim.x;
    for (size_t c = g; c < n16; c += gs) {
        const float4* s4 = (const float4*)(src + c * 16);
        float4 v[4];
#pragma unroll
        for (int j = 0; j < 4; ++j) v[j] = s4[j];
        uint2* d4 = (uint2*)(dst + c * 16);
#pragma unroll
        for (int j = 0; j < 4; ++j) {
            __half f[4];
            f[0] = __float2half_rn(v[j].x);
            f[1] = __float2half_rn(v[j].y);
            f[2] = __float2half_rn(v[j].z);
            f[3] = __float2half_rn(v[j].w);
            d4[j] = *(uint2*)f;
        }
    }
}

// ---------------- warp-MMA helpers ------------------------------------------
__device__ __forceinline__ uint32_t smem_u32(const void* p) {
    uint32_t a;
    asm("{ .reg .u64 t; cvta.to.shared.u64 t, %1; cvt.u32.u64 %0, t; }"
        : "=r"(a) : "l"(p));
    return a;
}

__device__ __forceinline__ void cp16(uint32_t s, const void* g) {
    asm volatile("cp.async.cg.shared.global [%0], [%1], 16;"
                 :: "r"(s), "l"(g) : "memory");
}
#define CP_COMMIT() asm volatile("cp.async.commit_group;" ::: "memory")
template <int N>
__device__ __forceinline__ void cp_wait() {
    asm volatile("cp.async.wait_group %0;" :: "n"(N) : "memory");
}

__device__ __forceinline__ void ldsm4(uint32_t* r, uint32_t a) {
    asm volatile("ldmatrix.sync.aligned.m8n8.x4.shared.b16 {%0,%1,%2,%3}, [%4];"
                 : "=r"(r[0]), "=r"(r[1]), "=r"(r[2]), "=r"(r[3]) : "r"(a));
}
__device__ __forceinline__ void ldsm4t(uint32_t* r, uint32_t a) {
    asm volatile("ldmatrix.sync.aligned.m8n8.x4.trans.shared.b16 {%0,%1,%2,%3}, [%4];"
                 : "=r"(r[0]), "=r"(r[1]), "=r"(r[2]), "=r"(r[3]) : "r"(a));
}

__device__ __forceinline__ void mma_f16(float* c, const uint32_t* a,
                                        uint32_t b0, uint32_t b1) {
    asm volatile(
        "mma.sync.aligned.m16n8k16.row.col.f32.f16.f16.f32 "
        "{%0,%1,%2,%3}, {%4,%5,%6,%7}, {%8,%9}, {%0,%1,%2,%3};"
        : "+f"(c[0]), "+f"(c[1]), "+f"(c[2]), "+f"(c[3])
        : "r"(a[0]), "r"(a[1]), "r"(a[2]), "r"(a[3]), "r"(b0), "r"(b1));
}

__device__ __forceinline__ float swiglu_f(float g, float u) {
    return (g / (1.0f + expf(-g))) * u;
}

// A-tile swizzle (128B rows)
__device__ __forceinline__ uint32_t swzA(uint32_t off) {
    return off ^ ((off >> 3) & 0x70u);
}

// =============================================================================
// FUSED gate+up GEMM (fp16 single-pass). A k-major [M][K]; B natural [K][N]
// via ldmatrix.trans. Epilogue -> fp16 swiglu acts.
// CTA 128x128, KC=64, 3 stages (48KB/stage), 8 warps (2x4), warp tile 64x32.
// =============================================================================
template <bool ROUTED, bool GATHER>
__global__ void __launch_bounds__(256, 1)
mma_fused(const __half* __restrict__ Af,
          const __half* __restrict__ B1f, const __half* __restrict__ B2f,
          __half* __restrict__ Ohf, int K, int N, int fixedM)
{
    constexpr int KC   = 64;
    constexpr int TILE = KC * 256;     // 16 KB
    constexpr int STG  = 3 * TILE;     // 48 KB
    constexpr int OF_B1 = TILE;
    constexpr int OF_B2 = 2 * TILE;

    extern __shared__ char smem[];
    const int tid  = threadIdx.x;
    const int wid  = tid >> 5;
    const int lane = tid & 31;

    const int e = blockIdx.z;
    int M, seg;
    if (ROUTED) { M = g_cnt[e]; seg = g_off[e]; }
    else        { M = fixedM;   seg = 0; }
    const int mbase = blockIdx.y * 128;
    if (mbase >= M) return;
    const int nbase = blockIdx.x * 128;

    const uint32_t sb = smem_u32(smem);

    const int lrow = tid >> 1;
    const int hbA  = (tid & 1) * 64;
    uint32_t soA[4];
#pragma unroll
    for (int j = 0; j < 4; ++j)
        soA[j] = swzA((uint32_t)lrow * 128u + (uint32_t)hbA + j * 16u);

    int arow;
    {
        bool v = (mbase + lrow) < M;
        if (ROUTED) {
            int slot = seg + mbase + lrow;
            if (GATHER) arow = v ? g_rowtok[slot] : 0;
            else        arow = v ? slot : seg;
        } else arow = mbase + lrow;
    }
    const char* gA = (const char*)(Af + (size_t)arow * K) + hbA;

    const int bk  = tid >> 2;
    const int bnb = (tid & 3) * 64;
    uint32_t soB[4];
#pragma unroll
    for (int j = 0; j < 4; ++j)
        soB[j] = (uint32_t)bk * 256u + (((uint32_t)bnb + j * 16u) ^ (((uint32_t)bk & 7u) << 4));

    const size_t bexp = ROUTED ? (size_t)e * (size_t)K * (size_t)N : 0;
    const size_t brow = bexp + (size_t)bk * N + nbase;
    const char* gB1 = (const char*)(B1f + brow) + bnb;
    const char* gB2 = (const char*)(B2f + brow) + bnb;
    const size_t bstep = (size_t)KC * N * 2;

    const int nk = K / KC;

#define ISSUE_F(slot, kt)                                                       \
    do {                                                                        \
        uint32_t b_ = sb + (uint32_t)(slot) * STG;                              \
        size_t ak_ = (size_t)(kt) * 128;                                        \
        size_t bk_ = (size_t)(kt) * bstep;                                      \
        _Pragma("unroll")                                                       \
        for (int j_ = 0; j_ < 4; ++j_) {                                        \
            cp16(b_ + soA[j_],         gA  + ak_ + j_ * 16);                    \
            cp16(b_ + OF_B1 + soB[j_], gB1 + bk_ + j_ * 16);                    \
            cp16(b_ + OF_B2 + soB[j_], gB2 + bk_ + j_ * 16);                    \
        }                                                                       \
        CP_COMMIT();                                                            \
    } while (0)

    const int wm = (wid >> 2) * 64;
    const int wn = (wid & 3) * 32;

    uint32_t aOff[4];
#pragma unroll
    for (int mf = 0; mf < 4; ++mf)
        aOff[mf] = (uint32_t)(wm + mf * 16 + (lane & 15)) * 128u
                 + (uint32_t)((lane >> 4) * 16);
    uint32_t bB[2];
    {
        uint32_t r = lane & 7u, m = lane >> 3;
#pragma unroll
        for (int nf2 = 0; nf2 < 2; ++nf2) {
            uint32_t nb = (uint32_t)(wn + nf2 * 16 + (int)((m >> 1) * 8)) * 2u;
            bB[nf2] = ((m & 1u) * 8u + r) * 256u + (nb ^ (r << 4));
        }
    }

    float accG[4][4][4], accU[4][4][4];
#pragma unroll
    for (int i = 0; i < 4; ++i)
#pragma unroll
        for (int j = 0; j < 4; ++j)
#pragma unroll
            for (int q = 0; q < 4; ++q) { accG[i][j][q] = 0.f; accU[i][j][q] = 0.f; }

    ISSUE_F(0, 0);
    ISSUE_F(1, 1);

    for (int kt = 0; kt < nk; ++kt) {
        const int s = kt % 3;
        if (kt + 1 < nk) cp_wait<1>(); else cp_wait<0>();
        __syncthreads();
        if (kt + 2 < nk) ISSUE_F((kt + 2) % 3, kt + 2);

        const uint32_t stb = sb + (uint32_t)s * STG;
#pragma unroll
        for (int ks = 0; ks < 4; ++ks) {
            uint32_t a[4][4], b1[2][4], b2[2][4];
#pragma unroll
            for (int mf = 0; mf < 4; ++mf)
                ldsm4(a[mf], stb + swzA(aOff[mf] + ks * 32u));
#pragma unroll
            for (int nf2 = 0; nf2 < 2; ++nf2) {
                uint32_t off = bB[nf2] + ks * 4096u;
                ldsm4t(b1[nf2], stb + OF_B1 + off);
                ldsm4t(b2[nf2], stb + OF_B2 + off);
            }
#pragma unroll
            for (int mf = 0; mf < 4; ++mf)
#pragma unroll
                for (int nf = 0; nf < 4; ++nf)
                    mma_f16(accG[mf][nf], a[mf],
                            b1[nf >> 1][(nf & 1) * 2], b1[nf >> 1][(nf & 1) * 2 + 1]);
#pragma unroll
            for (int mf = 0; mf < 4; ++mf)
#pragma unroll
                for (int nf = 0; nf < 4; ++nf)
                    mma_f16(accU[mf][nf], a[mf],
                            b2[nf >> 1][(nf & 1) * 2], b2[nf >> 1][(nf & 1) * 2 + 1]);
        }
    }
#undef ISSUE_F

    const size_t rowoff = ROUTED ? (size_t)seg : 0;
#pragma unroll
    for (int mf = 0; mf < 4; ++mf) {
#pragma unroll
        for (int nf = 0; nf < 4; ++nf) {
            int r0 = mbase + wm + mf * 16 + (lane >> 2);
            int n0 = nbase + wn + nf * 8 + (lane & 3) * 2;
            float* cg = accG[mf][nf];
            float* cu = accU[mf][nf];
#pragma unroll
            for (int h = 0; h < 2; ++h) {
                int r = r0 + h * 8;
                if (r < M) {
                    size_t idx = (rowoff + r) * (size_t)N + n0;
                    float a0 = swiglu_f(cg[h * 2 + 0], cu[h * 2 + 0]);
                    float a1 = swiglu_f(cg[h * 2 + 1], cu[h * 2 + 1]);
                    __half2 hp = __floats2half2_rn(a0, a1);
                    *(uint32_t*)&Ohf[idx] = *reinterpret_cast<uint32_t*>(&hp);
                }
            }
        }
    }
}

// =============================================================================
// DOWN GEMM (fp16 single-pass). A k-major; B natural [K][N]; out fp32.
// CTA 128x128, KC=64, 3 stages (32KB/stage).
// =============================================================================
template <bool ROUTED>
__global__ void __launch_bounds__(256, 1)
mma_down(const __half* __restrict__ Af, const __half* __restrict__ Bf,
         float* __restrict__ Cf, int K, int N, int fixedM)
{
    constexpr int KC   = 64;
    constexpr int TILE = KC * 256;
    constexpr int STG  = 2 * TILE;     // 32 KB
    constexpr int OF_B = TILE;

    extern __shared__ char smem[];
    const int tid  = threadIdx.x;
    const int wid  = tid >> 5;
    const int lane = tid & 31;

    const int e = blockIdx.z;
    int M, seg;
    if (ROUTED) { M = g_cnt[e]; seg = g_off[e]; }
    else        { M = fixedM;   seg = 0; }
    const int mbase = blockIdx.y * 128;
    if (mbase >= M) return;
    const int nbase = blockIdx.x * 128;

    const uint32_t sb = smem_u32(smem);

    const int lrow = tid >> 1;
    const int hbA  = (tid & 1) * 64;
    uint32_t soA[4];
#pragma unroll
    for (int j = 0; j < 4; ++j)
        soA[j] = swzA((uint32_t)lrow * 128u + (uint32_t)hbA + j * 16u);

    int arow;
    {
        bool v = (mbase + lrow) < M;
        if (ROUTED) arow = v ? (seg + mbase + lrow) : seg;
        else        arow = mbase + lrow;
    }
    const char* gA = (const char*)(Af + (size_t)arow * K) + hbA;

    const int bk  = tid >> 2;
    const int bnb = (tid & 3) * 64;
    uint32_t soB[4];
#pragma unroll
    for (int j = 0; j < 4; ++j)
        soB[j] = (uint32_t)bk * 256u + (((uint32_t)bnb + j * 16u) ^ (((uint32_t)bk & 7u) << 4));

    const size_t bexp = ROUTED ? (size_t)e * (size_t)K * (size_t)N : 0;
    const size_t brow = bexp + (size_t)bk * N + nbase;
    const char* gB = (const char*)(Bf + brow) + bnb;
    const size_t bstep = (size_t)KC * N * 2;

    const int nk = K / KC;

#define ISSUE_D(slot, kt)                                                       \
    do {                                                                        \
        uint32_t b_ = sb + (uint32_t)(slot) * STG;                              \
        size_t ak_ = (size_t)(kt) * 128;                                        \
        size_t bk_ = (size_t)(kt) * bstep;                                      \
        _Pragma("unroll")                                                       \
        for (int j_ = 0; j_ < 4; ++j_) {                                        \
            cp16(b_ + soA[j_],        gA + ak_ + j_ * 16);                      \
            cp16(b_ + OF_B + soB[j_], gB + bk_ + j_ * 16);                      \
        }                                                                       \
        CP_COMMIT();                                                            \
    } while (0)

    const int wm = (wid >> 2) * 64;
    const int wn = (wid & 3) * 32;

    uint32_t aOff[4];
#pragma unroll
    for (int mf = 0; mf < 4; ++mf)
        aOff[mf] = (uint32_t)(wm + mf * 16 + (lane & 15)) * 128u
                 + (uint32_t)((lane >> 4) * 16);
    uint32_t bB[2];
    {
        uint32_t r = lane & 7u, m = lane >> 3;
#pragma unroll
        for (int nf2 = 0; nf2 < 2; ++nf2) {
            uint32_t nb = (uint32_t)(wn + nf2 * 16 + (int)((m >> 1) * 8)) * 2u;
            bB[nf2] = ((m & 1u) * 8u + r) * 256u + (nb ^ (r << 4));
        }
    }

    float acc[4][4][4];
#pragma unroll
    for (int i = 0; i < 4; ++i)
#pragma unroll
        for (int j = 0; j < 4; ++j)
#pragma unroll
            for (int q = 0; q < 4; ++q) acc[i][j][q] = 0.f;

    ISSUE_D(0, 0);
    ISSUE_D(1, 1);

    for (int kt = 0; kt < nk; ++kt) {
        const int s = kt % 3;
        if (kt + 1 < nk) cp_wait<1>(); else cp_wait<0>();
        __syncthreads();
        if (kt + 2 < nk) ISSUE_D((kt + 2) % 3, kt + 2);

        const uint32_t stb = sb + (uint32_t)s * STG;
#pragma unroll
        for (int ks = 0; ks < 4; ++ks) {
            uint32_t a[4][4], b[2][4];
#pragma unroll
            for (int mf = 0; mf < 4; ++mf)
                ldsm4(a[mf], stb + swzA(aOff[mf] + ks * 32u));
#pragma unroll
            for (int nf2 = 0; nf2 < 2; ++nf2)
                ldsm4t(b[nf2], stb + OF_B + bB[nf2] + ks * 4096u);
#pragma unroll
            for (int mf = 0; mf < 4; ++mf)
#pragma unroll
                for (int nf = 0; nf < 4; ++nf)
                    mma_f16(acc[mf][nf], a[mf],
                            b[nf >> 1][(nf & 1) * 2], b[nf >> 1][(nf & 1) * 2 + 1]);
        }
    }
#undef ISSUE_D

    const size_t rowoff = ROUTED ? (size_t)seg : 0;
#pragma unroll
    for (int mf = 0; mf < 4; ++mf) {
#pragma unroll
        for (int nf = 0; nf < 4; ++nf) {
            int r0 = mbase + wm + mf * 16 + (lane >> 2);
            int n0 = nbase + wn + nf * 8 + (lane & 3) * 2;
            float* c = acc[mf][nf];
            if (r0 < M)
                *(float2*)&Cf[(rowoff + r0) * (size_t)N + n0] = make_float2(c[0], c[1]);
            if (r0 + 8 < M)
                *(float2*)&Cf[(rowoff + r0 + 8) * (size_t)N + n0] = make_float2(c[2], c[3]);
        }
    }
}

// ---------------- combine: out += w0*Y[slot0] + w1*Y[slot1] ------------------
__global__ void combine_kernel(float* __restrict__ out) {
    int t = blockIdx.y;
    int c = (blockIdx.x * blockDim.x + threadIdx.x) * 4;
    int s0 = g_slot[2 * t + 0], s1 = g_slot[2 * t + 1];
    float w0 = g_wgt[2 * t + 0], w1 = g_wgt[2 * t + 1];
    const float4 y0 = *(const float4*)&g_Y[(size_t)s0 * H_DIM + c];
    const float4 y1 = *(const float4*)&g_Y[(size_t)s1 * H_DIM + c];
    float4 o = *(float4*)&out[(size_t)t * H_DIM + c];
    o.x += w0 * y0.x + w1 * y1.x;
    o.y += w0 * y0.y + w1 * y1.y;
    o.z += w0 * y0.z + w1 * y1.z;
    o.w += w0 * y0.w + w1 * y1.w;
    *(float4*)&out[(size_t)t * H_DIM + c] = o;
}

// ---------------- launch -----------------------------------------------------
extern "C" void kernel_launch(void* const* d_in, const int* in_sizes, int n_in,
                              void* d_out, int out_size) {
    (void)in_sizes; (void)n_in; (void)out_size;
    const float* x      = (const float*)d_in[0];
    // d_in[1] router_w, d_in[2] router_b: dead inputs (RandomSTE forward = noise)
    const float* w_gate = (const float*)d_in[3];
    const float* w_up   = (const float*)d_in[4];
    const float* w_down = (const float*)d_in[5];
    const float* sg     = (const float*)d_in[6];
    const float* su     = (const float*)d_in[7];
    const float* sd     = (const float*)d_in[8];
    float* out = (float*)d_out;

    auto sym = [](const void* s) {
        void* p = nullptr;
        cudaGetSymbolAddress(&p, s);
        return p;
    };
    __half* xf  = (__half*)sym(g_xf);
    __half* sgf = (__half*)sym(g_sgf);
    __half* suf = (__half*)sym(g_suf);
    __half* sdf = (__half*)sym(g_sdf);
    __half* wgf = (__half*)sym(g_wgf);
    __half* wuf = (__half*)sym(g_wuf);
    __half* wdf = (__half*)sym(g_wdf);
    __half* hsf = (__half*)sym(g_hsf);
    __half* hrf = (__half*)sym(g_hrf);
    float*  Yp  = (float*)sym(g_Y);

    const int SM_F = 3 * 3 * (64 * 256);   // 147456
    const int SM_D = 3 * 2 * (64 * 256);   // 98304

    // One-time host-object setup; the capture call performs ZERO creations.
    static cudaStream_t s2 = nullptr;
    static cudaEvent_t evX, evR;
    if (s2 == nullptr) {
        cudaFuncSetAttribute((const void*)mma_fused<false, false>,
                             cudaFuncAttributeMaxDynamicSharedMemorySize, SM_F);
        cudaFuncSetAttribute((const void*)mma_fused<true, true>,
                             cudaFuncAttributeMaxDynamicSharedMemorySize, SM_F);
        cudaFuncSetAttribute((const void*)mma_down<false>,
                             cudaFuncAttributeMaxDynamicSharedMemorySize, SM_D);
        cudaFuncSetAttribute((const void*)mma_down<true>,
                             cudaFuncAttributeMaxDynamicSharedMemorySize, SM_D);
        cudaStreamCreateWithFlags(&s2, cudaStreamNonBlocking);
        cudaEventCreateWithFlags(&evX, cudaEventDisableTiming);
        cudaEventCreateWithFlags(&evR, cudaEventDisableTiming);
    }

    auto convGrid = [](size_t n) { return (unsigned)(n / (256 * 16)); };

    // routed grid y: 12 blocks = 1536 rows/expert headroom (counts are
    // deterministic: mean 512, sigma ~22 -> enormous margin)
    const int YRT = 12;

    // ---- legacy stream: x conversion, then fork marker
    conv_f16<<<convGrid((size_t)T_TOKENS * H_DIM), 256>>>(
        x, xf, (size_t)T_TOKENS * H_DIM / 16);
    cudaEventRecord(evX, 0);

    // ---- stream 2: routing + expert weight conversions + routed GEMMs
    zero_kernel<<<1, 32, 0, s2>>>();
    route_kernel<<<T_TOKENS / 256, 256, 0, s2>>>();
    scan_kernel<<<1, 1, 0, s2>>>();
    scatter_kernel<<<T_TOKENS / 256, 256, 0, s2>>>();
    conv_f16<<<convGrid((size_t)E_NUM * H_DIM * I_DIM), 256, 0, s2>>>(
        w_gate, wgf, (size_t)E_NUM * H_DIM * I_DIM / 16);
    conv_f16<<<convGrid((size_t)E_NUM * H_DIM * I_DIM), 256, 0, s2>>>(
        w_up, wuf, (size_t)E_NUM * H_DIM * I_DIM / 16);
    conv_f16<<<convGrid((size_t)E_NUM * I_DIM * H_DIM), 256, 0, s2>>>(
        w_down, wdf, (size_t)E_NUM * I_DIM * H_DIM / 16);
    cudaStreamWaitEvent(s2, evX, 0);   // routed GEMMs need xf
    mma_fused<true, true>
        <<<dim3(I_DIM / 128, YRT, E_NUM), 256, SM_F, s2>>>(
            xf, wgf, wuf, hrf, H_DIM, I_DIM, 0);
    mma_down<true>
        <<<dim3(H_DIM / 128, YRT, E_NUM), 256, SM_D, s2>>>(
            hrf, wdf, Yp, I_DIM, H_DIM, 0);
    cudaEventRecord(evR, s2);

    // ---- legacy stream: shared path
    conv_f16<<<convGrid((size_t)H_DIM * SI_DIM), 256>>>(
        sg, sgf, (size_t)H_DIM * SI_DIM / 16);
    conv_f16<<<convGrid((size_t)H_DIM * SI_DIM), 256>>>(
        su, suf, (size_t)H_DIM * SI_DIM / 16);
    conv_f16<<<convGrid((size_t)SI_DIM * H_DIM), 256>>>(
        sd, sdf, (size_t)SI_DIM * H_DIM / 16);
    mma_fused<false, false>
        <<<dim3(SI_DIM / 128, T_TOKENS / 128, 1), 256, SM_F>>>(
            xf, sgf, suf, hsf, H_DIM, SI_DIM, T_TOKENS);
    mma_down<false>
        <<<dim3(H_DIM / 128, T_TOKENS / 128, 1), 256, SM_D>>>(
            hsf, sdf, out, SI_DIM, H_DIM, T_TOKENS);

    // ---- join: combine needs routed Y (s2) and shared out (legacy)
    cudaStreamWaitEvent(0, evR, 0);
    combine_kernel<<<dim3(H_DIM / 1024, T_TOKENS), 256>>>(out);
}